// round 1
// baseline (speedup 1.0000x reference)
#include <cuda_runtime.h>
#include <cuda_bf16.h>

// Problem shapes (fixed by the dataset):
//   out_matrix, label_matrix: [n, n, B] fp32 with n=64, B=256
//   margin: scalar fp32, sample_num: scalar (== n, unused)
// Outputs: loss (fp32 scalar), correction_num (count, written as fp32)

#define N      64     // n
#define NB     256    // batch
#define BCHUNK 32     // batches per block
#define NBLOCKS (N * (NB / BCHUNK))   // 64 * 8 = 512

__device__ float g_ploss[NBLOCKS];
__device__ int   g_pcnt[NBLOCKS];

__global__ void __launch_bounds__(256)
pair_loss_kernel(const float* __restrict__ outm,
                 const float* __restrict__ labm,
                 const float* __restrict__ marginp)
{
    __shared__ float so[N * BCHUNK];   // [j][b_local]
    __shared__ float sl[N * BCHUNK];
    __shared__ float red[256];
    __shared__ int   scnt;

    const int bid = blockIdx.x;
    const int r   = bid >> 3;            // row index 0..63
    const int bc  = (bid & 7) * BCHUNK;  // batch chunk base
    const int tid = threadIdx.x;
    const float margin = __ldg(marginp);

    // Stage the 64 x 32 tile for this (r, batch-chunk). Global layout:
    // elem(r, j, b) at ((r*N + j)*NB + b). 32 consecutive floats per (r,j)
    // -> one 128B transaction per row, fully coalesced.
    for (int idx = tid; idx < N * BCHUNK; idx += 256) {
        const int j  = idx >> 5;
        const int bl = idx & 31;
        const int g  = (r * N + j) * NB + bc + bl;
        so[idx] = outm[g];
        sl[idx] = labm[g];
    }
    if (tid == 0) scnt = 0;
    __syncthreads();

    const int lane = tid & 31;   // batch within chunk
    const int w    = tid >> 5;   // warp -> j-range [8w, 8w+8)

    // Preload this warp's 8 j-values for this lane's batch.
    float oj[8], lj[8];
    #pragma unroll
    for (int u = 0; u < 8; u++) {
        oj[u] = so[(w * 8 + u) * BCHUNK + lane];
        lj[u] = sl[(w * 8 + u) * BCHUNK + lane];
    }

    // All ordered (j,k) pairs, including the diagonal (contributes margin,
    // matching the reference). Two accumulators break the FADD chain.
    float acc0 = 0.f, acc1 = 0.f;
    for (int k = 0; k < N; k++) {
        const float ok = so[k * BCHUNK + lane];
        const float lk = sl[k * BCHUNK + lane];
        #pragma unroll
        for (int u = 0; u < 8; u += 2) {
            // margin - (oj-ok)*(lj-lk) == fma(ok-oj, lj-lk, margin)
            const float a0 = ok - oj[u];
            const float b0 = lj[u] - lk;
            acc0 += fmaxf(fmaf(a0, b0, margin), 0.f);
            const float a1 = ok - oj[u + 1];
            const float b1 = lj[u + 1] - lk;
            acc1 += fmaxf(fmaf(a1, b1, margin), 0.f);
        }
    }

    // Argmax-equality count: warp 0, one lane per batch. Strict '>' keeps
    // the FIRST max index, matching jnp.argmax semantics.
    if (w == 0) {
        float obest = so[lane];             int oidx = 0;
        float lbest = sl[lane];             int lidx = 0;
        for (int k = 1; k < N; k++) {
            const float ov = so[k * BCHUNK + lane];
            if (ov > obest) { obest = ov; oidx = k; }
            const float lv = sl[k * BCHUNK + lane];
            if (lv > lbest) { lbest = lv; lidx = k; }
        }
        const unsigned ball = __ballot_sync(0xffffffffu, oidx == lidx);
        if (lane == 0) scnt = __popc(ball);
    }

    // Deterministic block reduction (fixed tree order, no atomics).
    red[tid] = acc0 + acc1;
    __syncthreads();
    #pragma unroll
    for (int s = 128; s > 0; s >>= 1) {
        if (tid < s) red[tid] += red[tid + s];
        __syncthreads();
    }
    if (tid == 0) {
        g_ploss[bid] = red[0];
        g_pcnt[bid]  = scnt;
    }
}

__global__ void __launch_bounds__(256)
finalize_kernel(float* __restrict__ out, int out_size)
{
    __shared__ float red[256];
    __shared__ int   ired[256];
    const int tid = threadIdx.x;
    red[tid]  = g_ploss[tid] + g_ploss[tid + 256];
    ired[tid] = g_pcnt[tid]  + g_pcnt[tid + 256];
    __syncthreads();
    #pragma unroll
    for (int s = 128; s > 0; s >>= 1) {
        if (tid < s) { red[tid] += red[tid + s]; ired[tid] += ired[tid + s]; }
        __syncthreads();
    }
    if (tid == 0) {
        out[0] = red[0];
        if (out_size > 1) out[1] = (float)ired[0];
    }
}

extern "C" void kernel_launch(void* const* d_in, const int* in_sizes, int n_in,
                              void* d_out, int out_size)
{
    const float* outm    = (const float*)d_in[0];
    const float* labm    = (const float*)d_in[1];
    const float* marginp = (const float*)d_in[2];
    (void)in_sizes; (void)n_in;

    pair_loss_kernel<<<NBLOCKS, 256>>>(outm, labm, marginp);
    finalize_kernel<<<1, 256>>>((float*)d_out, out_size);
}

// round 2
// speedup vs baseline: 1.4159x; 1.4159x over previous
#include <cuda_runtime.h>

// out_matrix, label_matrix: [n, n, B] fp32, n=64, B=256.
// loss = sum relu(margin - d*l) over [B,n,n,n] ordered pairs (incl. diagonal)
//      = 2 * S_triangle + B*n*n * relu(margin)           (term is (j,k)-symmetric)
// count = sum over (b, r) of [argmax_j out == argmax_j lab]

#define N 64
#define NB 256
#define BCHUNK 64
#define NPAIR (BCHUNK / 2)                 // 32 float2 lanes per row
#define NBLOCKS (N * (NB / BCHUNK))        // 256

typedef unsigned long long ull;

__device__ float    g_ploss[NBLOCKS];
__device__ int      g_pcnt[NBLOCKS];
__device__ unsigned g_done = 0;            // self-resetting arrival counter

__device__ __forceinline__ ull add2(ull a, ull b) {
    ull d; asm("add.rn.f32x2 %0, %1, %2;" : "=l"(d) : "l"(a), "l"(b)); return d;
}
__device__ __forceinline__ ull fma2(ull a, ull b, ull c) {
    ull d; asm("fma.rn.f32x2 %0, %1, %2, %3;" : "=l"(d) : "l"(a), "l"(b), "l"(c)); return d;
}
__device__ __forceinline__ float2 up2(ull v) {
    float2 r; asm("mov.b64 {%0, %1}, %2;" : "=f"(r.x), "=f"(r.y) : "l"(v)); return r;
}
__device__ __forceinline__ ull pk2(float x, float y) {
    ull v; asm("mov.b64 %0, {%1, %2};" : "=l"(v) : "f"(x), "f"(y)); return v;
}

__global__ void __launch_bounds__(256, 2)
fused_pair_loss_kernel(const float* __restrict__ outm,
                       const float* __restrict__ labm,
                       const float* __restrict__ marginp,
                       float* __restrict__ out, int out_size)
{
    __shared__ ull   so[N * NPAIR];    // packed out values  [j][bpair]   16 KB
    __shared__ ull   snl[N * NPAIR];   // packed NEGATED lab [j][bpair]   16 KB
    __shared__ float red[256];
    __shared__ int   ired[256];
    __shared__ int   scnt[2];
    __shared__ int   sdone;

    const int bid = blockIdx.x;
    const int r   = bid >> 2;              // row 0..63
    const int bc  = (bid & 3) * BCHUNK;    // batch-chunk base
    const int tid = threadIdx.x;
    const float margin = __ldg(marginp);
    ull m2; asm("mov.b64 %0, {%1, %1};" : "=l"(m2) : "f"(margin));

    // Stage row r for 64 batches. Coalesced float2 global loads.
    for (int idx = tid; idx < N * NPAIR; idx += 256) {
        const int j = idx >> 5, p = idx & 31;
        const int g = (r * N + j) * NB + bc + 2 * p;
        const float2 o = *(const float2*)(outm + g);
        const float2 l = *(const float2*)(labm + g);
        so[idx]  = pk2(o.x, o.y);
        snl[idx] = pk2(-l.x, -l.y);        // negated labels
    }
    __syncthreads();

    const int lane = tid & 31;             // batch-pair index
    const int w    = tid >> 5;             // warp id 0..7
    const ull sgn  = 0x8000000080000000ULL;

    float a0 = 0.f, a1 = 0.f, a2 = 0.f, a3 = 0.f;

    // Balanced triangle: (warp, q) owns complementary rows jlo = 4w+q and
    // jhi = 63-jlo. Pairs: (jlo, k) for k in (jlo, 63], (jhi, k) for k in
    // (jhi, 63]. Exactly 63 pair-iterations per q for every warp.
    #pragma unroll
    for (int q = 0; q < 4; q++) {
        const int jlo = w * 4 + q;
        const int jhi = 63 - jlo;
        const ull ojn = so[jlo * 32 + lane] ^ sgn;    // -o_jlo
        const ull ljp = snl[jlo * 32 + lane] ^ sgn;   // +l_jlo
        const ull ohn = so[jhi * 32 + lane] ^ sgn;    // -o_jhi
        const ull lhp = snl[jhi * 32 + lane] ^ sgn;   // +l_jhi

        // Segment A: k in [jlo+1, jhi] -> only pair (jlo, k)
        #pragma unroll 4
        for (int k = jlo + 1; k <= jhi; k++) {
            const ull ok  = so[k * 32 + lane];
            const ull nlk = snl[k * 32 + lane];
            // t = m + (ok - ojlo)*(ljlo - lk) = m - (ojlo-ok)(ljlo-lk)
            const float2 t = up2(fma2(add2(ok, ojn), add2(ljp, nlk), m2));
            a0 += fmaxf(t.x, 0.f);
            a1 += fmaxf(t.y, 0.f);
        }
        // Segment B: k in [jhi+1, 63] -> pairs (jlo, k) and (jhi, k)
        #pragma unroll 4
        for (int k = jhi + 1; k < 64; k++) {
            const ull ok  = so[k * 32 + lane];
            const ull nlk = snl[k * 32 + lane];
            const float2 t = up2(fma2(add2(ok, ojn), add2(ljp, nlk), m2));
            const float2 u = up2(fma2(add2(ok, ohn), add2(lhp, nlk), m2));
            a0 += fmaxf(t.x, 0.f);
            a1 += fmaxf(t.y, 0.f);
            a2 += fmaxf(u.x, 0.f);
            a3 += fmaxf(u.y, 0.f);
        }
    }

    // Argmax-equality count (warps 0,1; one lane per batch). Labels are
    // negated in SMEM, so argmax(lab) == first strict argmin(snl).
    if (w < 2) {
        const int bl = w * 32 + lane;
        const float* sof = (const float*)so;
        const float* snf = (const float*)snl;
        float ob = sof[bl]; int oi = 0;
        float lb = snf[bl]; int li = 0;
        for (int k = 1; k < 64; k++) {
            const float ov = sof[k * 64 + bl];
            if (ov > ob) { ob = ov; oi = k; }
            const float lv = snf[k * 64 + bl];
            if (lv < lb) { lb = lv; li = k; }
        }
        const unsigned ball = __ballot_sync(0xffffffffu, oi == li);
        if (lane == 0) scnt[w] = __popc(ball);
    }

    // Deterministic block tree reduction.
    red[tid] = (a0 + a1) + (a2 + a3);
    __syncthreads();
    #pragma unroll
    for (int s = 128; s > 0; s >>= 1) {
        if (tid < s) red[tid] += red[tid + s];
        __syncthreads();
    }

    if (tid == 0) {
        g_ploss[bid] = red[0];
        g_pcnt[bid]  = scnt[0] + scnt[1];
        __threadfence();
        const unsigned t = atomicAdd(&g_done, 1u);
        sdone = (t == NBLOCKS - 1);
    }
    __syncthreads();
    if (!sdone) return;

    // Last block: deterministic final reduce (fixed tree order).
    __threadfence();
    red[tid]  = g_ploss[tid];     // NBLOCKS == 256 == blockDim
    ired[tid] = g_pcnt[tid];
    __syncthreads();
    #pragma unroll
    for (int s = 128; s > 0; s >>= 1) {
        if (tid < s) { red[tid] += red[tid + s]; ired[tid] += ired[tid + s]; }
        __syncthreads();
    }
    if (tid == 0) {
        // diagonal (j==k) terms: B*n*n of them, each relu(margin)
        out[0] = 2.f * red[0] + 1048576.f * fmaxf(margin, 0.f);
        if (out_size > 1) out[1] = (float)ired[0];
        g_done = 0;               // reset for next graph replay
    }
}

extern "C" void kernel_launch(void* const* d_in, const int* in_sizes, int n_in,
                              void* d_out, int out_size)
{
    const float* outm    = (const float*)d_in[0];
    const float* labm    = (const float*)d_in[1];
    const float* marginp = (const float*)d_in[2];
    (void)in_sizes; (void)n_in;

    fused_pair_loss_kernel<<<NBLOCKS, 256>>>(outm, labm, marginp,
                                             (float*)d_out, out_size);
}

// round 3
// speedup vs baseline: 1.4636x; 1.0336x over previous
#include <cuda_runtime.h>

// out_matrix, label_matrix: [n, n, B] fp32, n=64, B=256.
// loss = sum_{b,r,j,k} relu(m - (o_j-o_k)(l_j-l_k))   (ordered pairs incl diagonal)
//      = sum_{b,r} [ S_t + S_abs ] + B*n*n*relu(m)
//   where over the strict upper triangle (j<k), t = m - x:
//     S_t   = 2016*m - (n*sum_j o_j l_j - (sum o)(sum l))   (analytic)
//     S_abs = sum |t|                                       (computed)
//   using 2*relu(t) = t + |t| and symmetry of x in (j,k).
// count = sum over (b,r) of [argmax_j out == argmax_j lab]

#define NBLOCKS 256
typedef unsigned long long ull;

__device__ float    g_ploss[NBLOCKS];
__device__ int      g_pcnt[NBLOCKS];
__device__ unsigned g_done = 0;

static __device__ __forceinline__ ull add2(ull a, ull b) {
    ull d; asm("add.rn.f32x2 %0, %1, %2;" : "=l"(d) : "l"(a), "l"(b)); return d;
}
static __device__ __forceinline__ ull fma2(ull a, ull b, ull c) {
    ull d; asm("fma.rn.f32x2 %0, %1, %2, %3;" : "=l"(d) : "l"(a), "l"(b), "l"(c)); return d;
}
static __device__ __forceinline__ float2 up2(ull v) {
    float2 r; asm("mov.b64 {%0, %1}, %2;" : "=f"(r.x), "=f"(r.y) : "l"(v)); return r;
}
static __device__ __forceinline__ ull pk2(float x, float y) {
    ull v; asm("mov.b64 %0, {%1, %2};" : "=l"(v) : "f"(x), "f"(y)); return v;
}

#define SGN  0x8000000080000000ULL
#define ABSM 0x7fffffff7fffffffULL

__global__ void __launch_bounds__(256, 3)
fused_pair_loss_kernel(const float* __restrict__ outm,
                       const float* __restrict__ labm,
                       const float* __restrict__ marginp,
                       float* __restrict__ out, int out_size)
{
    __shared__ ull   so[64 * 32];     // packed out       [j][bpair]  16 KB
    __shared__ ull   snl[64 * 32];    // packed -lab      [j][bpair]  16 KB
    __shared__ ull   pd_sol[256];     // per-warp dot partials        2 KB each
    __shared__ ull   pd_so[256];
    __shared__ ull   pd_sl[256];
    __shared__ ull   red[256];        // packed |t| reduction         2 KB
    __shared__ float fredf[256];      // final cross-block reduce     1 KB
    __shared__ int   ired[256];
    __shared__ int   scnt[2];
    __shared__ int   sdone;

    const int bid  = blockIdx.x;
    const int r    = bid >> 2;              // row 0..63
    const int bc   = (bid & 3) * 64;        // batch-chunk base
    const int tid  = threadIdx.x;
    const int lane = tid & 31;
    const int w    = tid >> 5;
    const float margin = __ldg(marginp);
    const ull m2 = pk2(margin, margin);

    // Stage row r for 64 batches (coalesced float2 loads).
    for (int idx = tid; idx < 64 * 32; idx += 256) {
        const int j = idx >> 5, p = idx & 31;
        const int g = (r * 64 + j) * 256 + bc + 2 * p;
        const float2 o = *(const float2*)(outm + g);
        const float2 l = *(const float2*)(labm + g);
        so[idx]  = pk2(o.x, o.y);
        snl[idx] = pk2(-l.x, -l.y);
    }
    __syncthreads();

    // Warp w owns rows jl..jl+3 and jh..jh+3. Uniform: 28 static pairs,
    // C loop (56-8w iters, 4 pairs each), D loop (4w iters, 8 pairs each)
    // -> exactly 252 pairs & 224 loop-pair computations per warp.
    const int jl = 4 * w;
    const int jh = 60 - 4 * w;

    ull ojn[8], ljp[8];   // -o_j, +l_j for the 8 owned rows
    #pragma unroll
    for (int a = 0; a < 4; a++) {
        ojn[a]     = so [(jl + a) * 32 + lane] ^ SGN;
        ljp[a]     = snl[(jl + a) * 32 + lane] ^ SGN;
        ojn[4 + a] = so [(jh + a) * 32 + lane] ^ SGN;
        ljp[4 + a] = snl[(jh + a) * 32 + lane] ^ SGN;
    }

    ull acc0 = 0, acc1 = 0, acc2 = 0, acc3 = 0;

    // 28 static register-resident pairs (row(i1) < row(i2) in every case).
    #pragma unroll
    for (int i1 = 0; i1 < 8; i1++) {
        #pragma unroll
        for (int i2 = i1 + 1; i2 < 8; i2++) {
            const ull a = add2(ojn[i1], ojn[i2] ^ SGN);   // o_k - o_j
            const ull b = add2(ljp[i1], ljp[i2] ^ SGN);   // l_j - l_k
            const ull t = fma2(a, b, m2);                 // m - x
            acc0 = add2(acc0, t & ABSM);
        }
    }

    // Per-warp dot partials for the analytic S_t term.
    ull nsol = 0, sOn = 0, sL = 0;
    #pragma unroll
    for (int i = 0; i < 8; i++) {
        nsol = fma2(ojn[i], ljp[i], nsol);   // -sum o*l
        sOn  = add2(sOn, ojn[i]);            // -sum o
        sL   = add2(sL,  ljp[i]);            // +sum l
    }
    pd_sol[tid] = nsol; pd_so[tid] = sOn; pd_sl[tid] = sL;

    // C: k between the two blocks -> 4 low-rows share each (ok, nlk).
    #pragma unroll 4
    for (int k = jl + 4; k < jh; k++) {
        const ull ok  = so [k * 32 + lane];
        const ull nlk = snl[k * 32 + lane];
        const ull t0 = fma2(add2(ok, ojn[0]), add2(ljp[0], nlk), m2);
        const ull t1 = fma2(add2(ok, ojn[1]), add2(ljp[1], nlk), m2);
        const ull t2 = fma2(add2(ok, ojn[2]), add2(ljp[2], nlk), m2);
        const ull t3 = fma2(add2(ok, ojn[3]), add2(ljp[3], nlk), m2);
        acc0 = add2(acc0, t0 & ABSM);
        acc1 = add2(acc1, t1 & ABSM);
        acc2 = add2(acc2, t2 & ABSM);
        acc3 = add2(acc3, t3 & ABSM);
    }

    // D: k past both blocks -> all 8 rows share each (ok, nlk).
    #pragma unroll 2
    for (int k = jh + 4; k < 64; k++) {
        const ull ok  = so [k * 32 + lane];
        const ull nlk = snl[k * 32 + lane];
        const ull t0 = fma2(add2(ok, ojn[0]), add2(ljp[0], nlk), m2);
        const ull t1 = fma2(add2(ok, ojn[1]), add2(ljp[1], nlk), m2);
        const ull t2 = fma2(add2(ok, ojn[2]), add2(ljp[2], nlk), m2);
        const ull t3 = fma2(add2(ok, ojn[3]), add2(ljp[3], nlk), m2);
        const ull t4 = fma2(add2(ok, ojn[4]), add2(ljp[4], nlk), m2);
        const ull t5 = fma2(add2(ok, ojn[5]), add2(ljp[5], nlk), m2);
        const ull t6 = fma2(add2(ok, ojn[6]), add2(ljp[6], nlk), m2);
        const ull t7 = fma2(add2(ok, ojn[7]), add2(ljp[7], nlk), m2);
        acc0 = add2(acc0, add2(t0 & ABSM, t4 & ABSM));
        acc1 = add2(acc1, add2(t1 & ABSM, t5 & ABSM));
        acc2 = add2(acc2, add2(t2 & ABSM, t6 & ABSM));
        acc3 = add2(acc3, add2(t3 & ABSM, t7 & ABSM));
    }

    // Argmax-equality (warps 0,1; one lane per batch; snl negated -> argmin).
    if (w < 2) {
        const int bl = w * 32 + lane;
        const float* sof = (const float*)so;
        const float* snf = (const float*)snl;
        float ob = sof[bl]; int oi = 0;
        float lb = snf[bl]; int li = 0;
        for (int k = 1; k < 64; k++) {
            const float ov = sof[k * 64 + bl];
            if (ov > ob) { ob = ov; oi = k; }
            const float lv = snf[k * 64 + bl];
            if (lv < lb) { lb = lv; li = k; }
        }
        const unsigned ball = __ballot_sync(0xffffffffu, oi == li);
        if (lane == 0) scnt[w] = __popc(ball);
    }

    // Packed |t| reduction across warps (fixed order, deterministic).
    red[tid] = add2(add2(acc0, acc1), add2(acc2, acc3));
    __syncthreads();
    if (tid < 128) red[tid] = add2(red[tid], red[tid + 128]);
    __syncthreads();
    if (tid < 64)  red[tid] = add2(red[tid], red[tid + 64]);
    __syncthreads();
    if (tid < 32)  red[tid] = add2(red[tid], red[tid + 32]);
    __syncwarp();

    float bl_loss = 0.f;
    if (tid < 32) {
        ull ns = pd_sol[tid], on = pd_so[tid], sl = pd_sl[tid];
        #pragma unroll
        for (int ww = 1; ww < 8; ww++) {
            ns = add2(ns, pd_sol[ww * 32 + tid]);
            on = add2(on, pd_so[ww * 32 + tid]);
            sl = add2(sl, pd_sl[ww * 32 + tid]);
        }
        const ull c64   = pk2(64.f, 64.f);
        const ull m2016 = pk2(2016.f * margin, 2016.f * margin);
        ull A = fma2(c64, ns, m2016);       // 2016m - 64*sum(o*l)
        A = fma2(on ^ SGN, sl, A);          // + (sum o)(sum l)
        const float2 f = up2(add2(red[tid], A));
        float v = f.x + f.y;
        v += __shfl_down_sync(0xffffffffu, v, 16);
        v += __shfl_down_sync(0xffffffffu, v, 8);
        v += __shfl_down_sync(0xffffffffu, v, 4);
        v += __shfl_down_sync(0xffffffffu, v, 2);
        v += __shfl_down_sync(0xffffffffu, v, 1);
        bl_loss = v;
    }

    if (tid == 0) {
        g_ploss[bid] = bl_loss;
        g_pcnt[bid]  = scnt[0] + scnt[1];
        __threadfence();
        const unsigned t = atomicAdd(&g_done, 1u);
        sdone = (t == NBLOCKS - 1);
    }
    __syncthreads();
    if (!sdone) return;

    // Last block: deterministic final reduce.
    __threadfence();
    fredf[tid] = g_ploss[tid];     // NBLOCKS == 256 == blockDim
    ired[tid]  = g_pcnt[tid];
    __syncthreads();
    #pragma unroll
    for (int s = 128; s > 0; s >>= 1) {
        if (tid < s) { fredf[tid] += fredf[tid + s]; ired[tid] += ired[tid + s]; }
        __syncthreads();
    }
    if (tid == 0) {
        // + diagonal: B*n*n terms of relu(margin)
        out[0] = fredf[0] + 1048576.f * fmaxf(margin, 0.f);
        if (out_size > 1) out[1] = (float)ired[0];
        g_done = 0;                // reset for next graph replay
    }
}

extern "C" void kernel_launch(void* const* d_in, const int* in_sizes, int n_in,
                              void* d_out, int out_size)
{
    const float* outm    = (const float*)d_in[0];
    const float* labm    = (const float*)d_in[1];
    const float* marginp = (const float*)d_in[2];
    (void)in_sizes; (void)n_in;

    fused_pair_loss_kernel<<<NBLOCKS, 256>>>(outm, labm, marginp,
                                             (float*)d_out, out_size);
}

// round 4
// speedup vs baseline: 1.4858x; 1.0152x over previous
#include <cuda_runtime.h>

// out_matrix, label_matrix: [n, n, B] fp32, n=64, B=256.
// loss = 2*S_tri + B*n*n*relu(m), S_tri computed as (S_t + S_abs)/... :
//   per (r, batch): over strict upper triangle, t = m - (o_j-o_k)(l_j-l_k)
//   sum(t + |t|) = 2*sum relu(t);  sum t = 2016*m - (64*sum o*l - sum_o*sum_l)
// count = sum over (b,r) of [argmax_j out == argmax_j lab]

#define NBLOCKS 256
typedef unsigned long long ull;

__device__ float    g_ploss[NBLOCKS];
__device__ int      g_pcnt[NBLOCKS];
__device__ unsigned g_done = 0;

static __device__ __forceinline__ ull add2(ull a, ull b) {
    ull d; asm("add.rn.f32x2 %0, %1, %2;" : "=l"(d) : "l"(a), "l"(b)); return d;
}
static __device__ __forceinline__ ull fma2(ull a, ull b, ull c) {
    ull d; asm("fma.rn.f32x2 %0, %1, %2, %3;" : "=l"(d) : "l"(a), "l"(b), "l"(c)); return d;
}
static __device__ __forceinline__ float2 up2(ull v) {
    float2 r; asm("mov.b64 {%0, %1}, %2;" : "=f"(r.x), "=f"(r.y) : "l"(v)); return r;
}
static __device__ __forceinline__ ull pk2(float x, float y) {
    ull v; asm("mov.b64 %0, {%1, %2};" : "=l"(v) : "f"(x), "f"(y)); return v;
}

#define SGN  0x8000000080000000ULL
#define ABSM 0x7fffffff7fffffffULL

__global__ void __launch_bounds__(512, 2)
fused_pair_loss_kernel(const float* __restrict__ outm,
                       const float* __restrict__ labm,
                       const float* __restrict__ marginp,
                       float* __restrict__ out, int out_size)
{
    __shared__ ull   so[64 * 32];     // packed out  [j][bpair]   16 KB
    __shared__ ull   snl[64 * 32];    // packed -lab [j][bpair]   16 KB
    __shared__ ull   pd_sol[512];     // per-thread dot partials  4 KB x3
    __shared__ ull   pd_so[512];
    __shared__ ull   pd_sl[512];
    __shared__ ull   red[512];        // packed |t|+... reduce    4 KB
    __shared__ float fredf[256];
    __shared__ int   ired[256];
    __shared__ int   scnt[2];
    __shared__ int   sdone;

    const int bid  = blockIdx.x;
    const int r    = bid >> 2;              // row 0..63
    const int bc   = (bid & 3) * 64;        // batch-chunk base
    const int tid  = threadIdx.x;
    const int lane = tid & 31;
    const int w    = tid >> 5;              // warp role 0..15
    const float margin = __ldg(marginp);
    const ull m2 = pk2(margin, margin);

    // Stage row r for 64 batches (coalesced float2 loads).
    for (int idx = tid; idx < 64 * 32; idx += 512) {
        const int j = idx >> 5, p = idx & 31;
        const int g = (r * 64 + j) * 256 + bc + 2 * p;
        const float2 o = *(const float2*)(outm + g);
        const float2 l = *(const float2*)(labm + g);
        so[idx]  = pk2(o.x, o.y);
        snl[idx] = pk2(-l.x, -l.y);
    }
    __syncthreads();

    // Warp w owns rows {2w, 2w+1, 62-2w, 63-2w} (ascending for all w<=15).
    // 6 static pairs + C loop (60-4w iters x 2 pairs) + D loop (2w x 4)
    // = 126 packed pairs per warp, exactly uniform.
    const int jl = 2 * w;
    const int jh = 62 - 2 * w;

    ull ojn[4], ljp[4];   // -o_row, +l_row for the 4 owned rows
    ojn[0] = so [(jl    ) * 32 + lane] ^ SGN;
    ojn[1] = so [(jl + 1) * 32 + lane] ^ SGN;
    ojn[2] = so [(jh    ) * 32 + lane] ^ SGN;
    ojn[3] = so [(jh + 1) * 32 + lane] ^ SGN;
    ljp[0] = snl[(jl    ) * 32 + lane] ^ SGN;
    ljp[1] = snl[(jl + 1) * 32 + lane] ^ SGN;
    ljp[2] = snl[(jh    ) * 32 + lane] ^ SGN;
    ljp[3] = snl[(jh + 1) * 32 + lane] ^ SGN;

    ull acc0 = 0, acc1 = 0, acc2 = 0, acc3 = 0;

    // 6 static pairs among the owned rows (row[i1] < row[i2] always).
    #pragma unroll
    for (int i1 = 0; i1 < 4; i1++) {
        #pragma unroll
        for (int i2 = i1 + 1; i2 < 4; i2++) {
            const ull a = add2(ojn[i1], ojn[i2] ^ SGN);   // o_k - o_j
            const ull b = add2(ljp[i1], ljp[i2] ^ SGN);   // l_j - l_k
            acc0 = add2(acc0, fma2(a, b, m2) & ABSM);
        }
    }

    // Per-lane dot partials for the analytic term (4 owned rows).
    {
        ull nsol = 0, sOn = 0, sL = 0;
        #pragma unroll
        for (int i = 0; i < 4; i++) {
            nsol = fma2(ojn[i], ljp[i], nsol);   // -sum o*l
            sOn  = add2(sOn, ojn[i]);            // -sum o
            sL   = add2(sL,  ljp[i]);            // +sum l
        }
        pd_sol[tid] = nsol; pd_so[tid] = sOn; pd_sl[tid] = sL;
    }

    // C: k strictly between the blocks -> pairs with the 2 low rows.
    #pragma unroll 4
    for (int k = jl + 2; k < jh; k++) {
        const ull ok  = so [k * 32 + lane];
        const ull nlk = snl[k * 32 + lane];
        const ull t0 = fma2(add2(ok, ojn[0]), add2(ljp[0], nlk), m2);
        const ull t1 = fma2(add2(ok, ojn[1]), add2(ljp[1], nlk), m2);
        acc0 = add2(acc0, t0 & ABSM);
        acc1 = add2(acc1, t1 & ABSM);
    }

    // D: k past both blocks -> pairs with all 4 owned rows.
    #pragma unroll 2
    for (int k = jh + 2; k < 64; k++) {
        const ull ok  = so [k * 32 + lane];
        const ull nlk = snl[k * 32 + lane];
        const ull t0 = fma2(add2(ok, ojn[0]), add2(ljp[0], nlk), m2);
        const ull t1 = fma2(add2(ok, ojn[1]), add2(ljp[1], nlk), m2);
        const ull t2 = fma2(add2(ok, ojn[2]), add2(ljp[2], nlk), m2);
        const ull t3 = fma2(add2(ok, ojn[3]), add2(ljp[3], nlk), m2);
        acc0 = add2(acc0, t0 & ABSM);
        acc1 = add2(acc1, t1 & ABSM);
        acc2 = add2(acc2, t2 & ABSM);
        acc3 = add2(acc3, t3 & ABSM);
    }

    // Argmax-equality (warps 0,1; one lane per batch; snl negated -> argmin).
    if (w < 2) {
        const int bl = w * 32 + lane;
        const float* sof = (const float*)so;
        const float* snf = (const float*)snl;
        float ob = sof[bl]; int oi = 0;
        float lb = snf[bl]; int li = 0;
        for (int k = 1; k < 64; k++) {
            const float ov = sof[k * 64 + bl];
            if (ov > ob) { ob = ov; oi = k; }
            const float lv = snf[k * 64 + bl];
            if (lv < lb) { lb = lv; li = k; }
        }
        const unsigned ball = __ballot_sync(0xffffffffu, oi == li);
        if (lane == 0) scnt[w] = __popc(ball);
    }

    // Packed |t| reduction across the 16 warps (fixed order, deterministic).
    red[tid] = add2(add2(acc0, acc1), add2(acc2, acc3));
    __syncthreads();
    if (tid < 256) red[tid] = add2(red[tid], red[tid + 256]);
    __syncthreads();
    if (tid < 128) red[tid] = add2(red[tid], red[tid + 128]);
    __syncthreads();
    if (tid < 64)  red[tid] = add2(red[tid], red[tid + 64]);
    __syncthreads();

    float bl_loss = 0.f;
    if (tid < 32) {
        ull s_abs = add2(red[tid], red[tid + 32]);
        ull ns = pd_sol[tid], on = pd_so[tid], sl = pd_sl[tid];
        #pragma unroll
        for (int ww = 1; ww < 16; ww++) {
            ns = add2(ns, pd_sol[ww * 32 + tid]);
            on = add2(on, pd_so[ww * 32 + tid]);
            sl = add2(sl,  pd_sl[ww * 32 + tid]);
        }
        const ull c64   = pk2(64.f, 64.f);
        const ull m2016 = pk2(2016.f * margin, 2016.f * margin);
        ull A = fma2(c64, ns, m2016);       // 2016m - 64*sum(o*l)
        A = fma2(on ^ SGN, sl, A);          // + (sum o)(sum l)
        const float2 f = up2(add2(s_abs, A));
        float v = f.x + f.y;
        v += __shfl_down_sync(0xffffffffu, v, 16);
        v += __shfl_down_sync(0xffffffffu, v, 8);
        v += __shfl_down_sync(0xffffffffu, v, 4);
        v += __shfl_down_sync(0xffffffffu, v, 2);
        v += __shfl_down_sync(0xffffffffu, v, 1);
        bl_loss = v;
    }

    if (tid == 0) {
        g_ploss[bid] = bl_loss;
        g_pcnt[bid]  = scnt[0] + scnt[1];
        __threadfence();
        const unsigned t = atomicAdd(&g_done, 1u);
        sdone = (t == NBLOCKS - 1);
    }
    __syncthreads();
    if (!sdone) return;

    // Last block: deterministic final reduce over the 256 block partials.
    __threadfence();
    if (tid < 256) { fredf[tid] = g_ploss[tid]; ired[tid] = g_pcnt[tid]; }
    __syncthreads();
    #pragma unroll
    for (int s = 128; s > 0; s >>= 1) {
        if (tid < s) { fredf[tid] += fredf[tid + s]; ired[tid] += ired[tid + s]; }
        __syncthreads();
    }
    if (tid == 0) {
        // + diagonal: B*n*n terms of relu(margin)
        out[0] = fredf[0] + 1048576.f * fmaxf(margin, 0.f);
        if (out_size > 1) out[1] = (float)ired[0];
        g_done = 0;                // reset for next graph replay
    }
}

extern "C" void kernel_launch(void* const* d_in, const int* in_sizes, int n_in,
                              void* d_out, int out_size)
{
    const float* outm    = (const float*)d_in[0];
    const float* labm    = (const float*)d_in[1];
    const float* marginp = (const float*)d_in[2];
    (void)in_sizes; (void)n_in;

    fused_pair_loss_kernel<<<NBLOCKS, 512>>>(outm, labm, marginp,
                                             (float*)d_out, out_size);
}